// round 14
// baseline (speedup 1.0000x reference)
#include <cuda_runtime.h>
#include <math.h>

#define NN 2048
#define MM 128
#define KD 8
#define K2 64
#define NPACK 36
#define NPB 4             // children per block (4 groups of 8 lanes in warp 0)
#define NB (NN / NPB)     // 512 chunks per t
#define NPAR 16           // parent producer blocks
#define FULLM 0xffffffffu

// ---------------- scratch --------------------------------------------------
__device__ float4 g_C4[2][11][MM];   // 44 coefs per m: 36 Bp + 8 (-h), SoA over m
__device__ float  g_dm[2][MM];       // -log|det O| + 0.5 logdetS - 4 + 0.5 ee
__device__ double g_part[2][NB];
__device__ volatile unsigned int g_ready;
__device__ unsigned int g_done;

// ---------------- f32x2 helpers --------------------------------------------
__device__ __forceinline__ void ffma2(unsigned long long& d,
                                      unsigned long long a, unsigned long long b) {
    asm("fma.rn.f32x2 %0, %1, %2, %0;" : "+l"(d) : "l"(a), "l"(b));
}
__device__ __forceinline__ float2 unpack2(unsigned long long v) {
    float2 f;
    asm("mov.b64 {%0, %1}, %2;" : "=f"(f.x), "=f"(f.y) : "l"(v));
    return f;
}

// ==================== single fused kernel ====================================
__global__ __launch_bounds__(128)
void main_kernel(const float* __restrict__ W,
                 const float* __restrict__ mu_p, const float* __restrict__ sigma_p,
                 const float* __restrict__ omega_child,
                 const float* __restrict__ mu_q, const float* __restrict__ sigma_q,
                 const float* __restrict__ omega_parent,
                 const float* __restrict__ mu_r, const float* __restrict__ sigma_r,
                 const float* __restrict__ omega_m_child,
                 const float* __restrict__ mu_s, const float* __restrict__ sigma_s,
                 const float* __restrict__ omega_m_parent,
                 float* __restrict__ out) {
    const int t  = blockIdx.y;
    const int m  = threadIdx.x;
    const int n0 = blockIdx.x * NPB;

    // ---- W prefetch first (longest latency; in flight through all phases) --
    float wv[NPB];
#pragma unroll
    for (int k = 0; k < NPB; k++) wv[k] = W[(n0 + k) * MM + m];

    // ================= parent phase: bids 0..15 of y==0 ====================
    if (blockIdx.y == 0 && blockIdx.x < NPAR) {
        const int g = m >> 3;     // group 0..15
        const int r = m & 7;
        const int gid = blockIdx.x * 16 + g;       // 0..255
        const int tp = gid >> 7;
        const int mp = gid & (MM - 1);
        const float* mup = (tp == 0) ? mu_q : mu_s;
        const float* Sp  = (tp == 0) ? sigma_q : sigma_s;
        const float* Op  = (tp == 0) ? omega_parent : omega_m_parent;

        float orow[KD], srow[KD], irow[KD], trow[KD];
        {
            const float4* o4 = reinterpret_cast<const float4*>(Op + (size_t)mp * K2 + r * KD);
            const float4* s4 = reinterpret_cast<const float4*>(Sp + (size_t)mp * K2 + r * KD);
            float4 a = o4[0], b = o4[1], c = s4[0], d = s4[1];
            orow[0] = a.x; orow[1] = a.y; orow[2] = a.z; orow[3] = a.w;
            orow[4] = b.x; orow[5] = b.y; orow[6] = b.z; orow[7] = b.w;
            srow[0] = c.x; srow[1] = c.y; srow[2] = c.z; srow[3] = c.w;
            srow[4] = d.x; srow[5] = d.y; srow[6] = d.z; srow[7] = d.w;
        }
        float mur = mup[mp * KD + r];
#pragma unroll
        for (int j = 0; j < KD; j++) irow[j] = (j == r) ? 1.f : 0.f;

        // row-parallel GJ inverse of SPD S; pivot product = det S
        float pdS = 1.f;
#pragma unroll
        for (int kk = 0; kk < KD; kk++) {
            float piv = __shfl_sync(FULLM, srow[kk], kk, 8);
            pdS *= piv;
            float ip = 1.f / piv;
            if (r == kk) {
#pragma unroll
                for (int j = 0; j < KD; j++) { srow[j] *= ip; irow[j] *= ip; }
            }
            float f = (r == kk) ? 0.f : srow[kk];
#pragma unroll
            for (int j = 0; j < KD; j++) {
                float ps = __shfl_sync(FULLM, srow[j], kk, 8);
                float pi = __shfl_sync(FULLM, irow[j], kk, 8);
                srow[j] = fmaf(-f, ps, srow[j]);
                irow[j] = fmaf(-f, pi, irow[j]);
            }
        }
        // u = Sinv*mu
        float ur = 0.f;
#pragma unroll
        for (int b = 0; b < KD; b++)
            ur = fmaf(irow[b], __shfl_sync(FULLM, mur, b, 8), ur);
        // T = Sinv*Omega (row r)
#pragma unroll
        for (int j = 0; j < KD; j++) trow[j] = 0.f;
#pragma unroll
        for (int b = 0; b < KD; b++) {
            float ib = irow[b];
#pragma unroll
            for (int j = 0; j < KD; j++)
                trow[j] = fmaf(ib, __shfl_sync(FULLM, orow[j], b, 8), trow[j]);
        }
        // ee = mu.u
        float ee = mur * ur;
        ee += __shfl_xor_sync(FULLM, ee, 1, 8);
        ee += __shfl_xor_sync(FULLM, ee, 2, 8);
        ee += __shfl_xor_sync(FULLM, ee, 4, 8);

        __shared__ float Osh[16][KD][KD], Tsh[16][KD][KD], ush[16][KD];
#pragma unroll
        for (int j = 0; j < KD; j++) { Osh[g][r][j] = orow[j]; Tsh[g][r][j] = trow[j]; }
        ush[g][r] = ur;
        __syncwarp();

        float* cbase = reinterpret_cast<float*>(g_C4) + (size_t)tp * 11 * MM * 4;
        const int pbase = r * KD - (r * (r - 1)) / 2 - r;
#pragma unroll
        for (int j = 0; j < KD; j++) {
            if (j < r) continue;
            float b = 0.f;
#pragma unroll
            for (int a = 0; a < KD; a++) b = fmaf(Osh[g][a][r], Tsh[g][a][j], b);
            if (j == r) b *= 0.5f;
            int c = pbase + j;
            cbase[(size_t)(c >> 2) * MM * 4 + mp * 4 + (c & 3)] = b;
        }
        {
            float h = 0.f;
#pragma unroll
            for (int a = 0; a < KD; a++) h = fmaf(Osh[g][a][r], ush[g][a], h);
            int c = NPACK + r;
            cbase[(size_t)(c >> 2) * MM * 4 + mp * 4 + (c & 3)] = -h;
        }
        // det Omega
        float pdO = 1.f;
#pragma unroll
        for (int kk = 0; kk < KD; kk++) {
            float piv = __shfl_sync(FULLM, orow[kk], kk, 8);
            pdO *= piv;
            float ipv = 1.f / piv;
            float f = (r > kk) ? orow[kk] * ipv : 0.f;
#pragma unroll
            for (int j = 0; j < KD; j++) {
                float pk = __shfl_sync(FULLM, orow[j], kk, 8);
                orow[j] = fmaf(-f, pk, orow[j]);
            }
        }
        if (r == 0)
            g_dm[tp][mp] = -logf(fabsf(pdO)) + 0.5f * logf(pdS) - 4.0f + 0.5f * ee;

        __threadfence();
        __syncthreads();
        if (m == 0) atomicAdd((unsigned int*)&g_ready, 1u);
    }

    // ================= child phase: warp 0, 4 groups of 8 ==================
    __shared__ __align__(16) float sh[NPB][48];
    if (m < 32) {
        const int grp = m >> 3;
        const int r   = m & 7;
        const int n   = n0 + grp;
        const float* muc = (t == 0) ? mu_p    : mu_r;
        const float* Sc  = (t == 0) ? sigma_p : sigma_r;
        const float* Oc  = (t == 0) ? omega_child : omega_m_child;

        float orow[KD], srow[KD], irow[KD];
        {
            const float4* o4 = reinterpret_cast<const float4*>(Oc + (size_t)n * K2 + r * KD);
            const float4* s4 = reinterpret_cast<const float4*>(Sc + (size_t)n * K2 + r * KD);
            float4 a = o4[0], b = o4[1], c = s4[0], d = s4[1];
            orow[0] = a.x; orow[1] = a.y; orow[2] = a.z; orow[3] = a.w;
            orow[4] = b.x; orow[5] = b.y; orow[6] = b.z; orow[7] = b.w;
            srow[0] = c.x; srow[1] = c.y; srow[2] = c.z; srow[3] = c.w;
            srow[4] = d.x; srow[5] = d.y; srow[6] = d.z; srow[7] = d.w;
        }
        float mur = muc[n * KD + r];
#pragma unroll
        for (int j = 0; j < KD; j++) irow[j] = (j == r) ? 1.f : 0.f;

        // row-parallel GJ: irow -> row r of Omega^{-1}
        float pd = 1.f;
#pragma unroll
        for (int kk = 0; kk < KD; kk++) {
            float piv = __shfl_sync(FULLM, orow[kk], kk, 8);
            pd *= piv;
            float ip = 1.f / piv;
            if (r == kk) {
#pragma unroll
                for (int j = 0; j < KD; j++) { orow[j] *= ip; irow[j] *= ip; }
            }
            float f = (r == kk) ? 0.f : orow[kk];
#pragma unroll
            for (int j = 0; j < KD; j++) {
                float pko = __shfl_sync(FULLM, orow[j], kk, 8);
                float pki = __shfl_sync(FULLM, irow[j], kk, 8);
                orow[j] = fmaf(-f, pko, orow[j]);
                irow[j] = fmaf(-f, pki, irow[j]);
            }
        }
        // v_r
        float vr = 0.f;
#pragma unroll
        for (int j = 0; j < KD; j++)
            vr = fmaf(irow[j], __shfl_sync(FULLM, mur, j, 8), vr);
        // trow = row r of Oi*S
        float trow[KD] = {0.f, 0.f, 0.f, 0.f, 0.f, 0.f, 0.f, 0.f};
#pragma unroll
        for (int b = 0; b < KD; b++) {
            float ob = irow[b];
#pragma unroll
            for (int c = 0; c < KD; c++)
                trow[c] = fmaf(ob, __shfl_sync(FULLM, srow[c], b, 8), trow[c]);
        }
        // Atilde row r -> packed upper in shared
        float* rec = &sh[grp][0];
        const int base = r * KD - (r * (r - 1)) / 2;
#pragma unroll
        for (int j = 0; j < KD; j++) {
            float aij = vr * __shfl_sync(FULLM, vr, j, 8);
#pragma unroll
            for (int c = 0; c < KD; c++)
                aij = fmaf(trow[c], __shfl_sync(FULLM, irow[c], j, 8), aij);
            if (j >= r) rec[base + j - r] = aij;
        }
        rec[NPACK + r] = vr;
        // det(S)
        float pd2 = 1.f;
#pragma unroll
        for (int kk = 0; kk < KD; kk++) {
            float piv = __shfl_sync(FULLM, srow[kk], kk, 8);
            pd2 *= piv;
            float ipv = 1.f / piv;
            float f = (r > kk) ? srow[kk] * ipv : 0.f;
#pragma unroll
            for (int j = 0; j < KD; j++) {
                float pks = __shfl_sync(FULLM, srow[j], kk, 8);
                srow[j] = fmaf(-f, pks, srow[j]);
            }
        }
        if (r == 0) rec[44] = logf(fabsf(pd)) - 0.5f * logf(pd2);
    }

    // ---- wait for parent coefs: exponential-backoff sleep (NOT busy spin) --
    if (m == 0) {
        if (g_ready < NPAR) {
            unsigned ns = 8;
            do {
                __nanosleep(ns);
                if (ns < 512) ns <<= 1;
            } while (g_ready < NPAR);
        }
    }
    __syncthreads();
    __threadfence();

    // ---- coef loads ----
    float4 c4[11];
#pragma unroll
    for (int q = 0; q < 11; q++) c4[q] = g_C4[t][q][m];
    const float dm = g_dm[t][m];
    const unsigned long long* c2 = reinterpret_cast<const unsigned long long*>(c4);

    // ---- pair phase ----
    float accf = 0.f;
#pragma unroll
    for (int k = 0; k < NPB; k++) {
        const unsigned long long* a2 =
            reinterpret_cast<const unsigned long long*>(&sh[k][0]);
        unsigned long long acc0 = 0ull, acc1 = 0ull;
#pragma unroll
        for (int p = 0; p < 22; p += 2) {
            ffma2(acc0, c2[p], a2[p]);
            ffma2(acc1, c2[p + 1], a2[p + 1]);
        }
        float2 s0 = unpack2(acc0);
        float2 s1 = unpack2(acc1);
        float kl = (s0.x + s0.y) + (s1.x + s1.y) + (dm + sh[k][44]);
        accf = fmaf(wv[k], kl, accf);
    }

    // ---- fp32 warp reduce -> fp64 block partial, ticket finalize ----
#pragma unroll
    for (int off = 16; off; off >>= 1)
        accf += __shfl_down_sync(FULLM, accf, off);
    __shared__ float wsumf[4];
    __shared__ int islast;
    if ((m & 31) == 0) wsumf[m >> 5] = accf;
    __syncthreads();
    if (m == 0) {
        g_part[t][blockIdx.x] =
            (double)wsumf[0] + (double)wsumf[1] + (double)wsumf[2] + (double)wsumf[3];
        __threadfence();
        unsigned int tick = atomicAdd(&g_done, 1u);
        islast = (tick == 2u * NB - 1u) ? 1 : 0;
    }
    __syncthreads();
    if (islast) {
        __threadfence();
        double s0 = g_part[0][m] + g_part[0][m + 128] +
                    g_part[0][m + 256] + g_part[0][m + 384];
        double s1 = g_part[1][m] + g_part[1][m + 128] +
                    g_part[1][m + 256] + g_part[1][m + 384];
#pragma unroll
        for (int off = 16; off; off >>= 1) {
            s0 += __shfl_down_sync(FULLM, s0, off);
            s1 += __shfl_down_sync(FULLM, s1, off);
        }
        __shared__ double ws0[4], ws1[4];
        if ((m & 31) == 0) { ws0[m >> 5] = s0; ws1[m >> 5] = s1; }
        __syncthreads();
        if (m == 0) {
            double b  = ws0[0] + ws0[1] + ws0[2] + ws0[3];
            double mo = ws1[0] + ws1[1] + ws1[2] + ws1[3];
            out[0] = (float)(b + mo);
            out[1] = (float)b;
            out[2] = (float)mo;
            g_done = 0u;     // reset for next graph replay
            g_ready = 0u;
        }
    }
}

// ----------------------------------------------------------------------------
extern "C" void kernel_launch(void* const* d_in, const int* in_sizes, int n_in,
                              void* d_out, int out_size) {
    const float* W              = (const float*)d_in[0];
    const float* mu_p           = (const float*)d_in[1];
    const float* sigma_p        = (const float*)d_in[2];
    const float* mu_q_parent    = (const float*)d_in[3];
    const float* sigma_q_parent = (const float*)d_in[4];
    const float* omega_child    = (const float*)d_in[5];
    const float* omega_parent   = (const float*)d_in[6];
    const float* mu_r           = (const float*)d_in[7];
    const float* sigma_r        = (const float*)d_in[8];
    const float* mu_s_parent    = (const float*)d_in[9];
    const float* sigma_s_parent = (const float*)d_in[10];
    const float* omega_m_child  = (const float*)d_in[11];
    const float* omega_m_parent = (const float*)d_in[12];

    main_kernel<<<dim3(NB, 2), MM>>>(W,
                                     mu_p, sigma_p, omega_child,
                                     mu_q_parent, sigma_q_parent, omega_parent,
                                     mu_r, sigma_r, omega_m_child,
                                     mu_s_parent, sigma_s_parent, omega_m_parent,
                                     (float*)d_out);
}

// round 15
// speedup vs baseline: 3.9101x; 3.9101x over previous
#include <cuda_runtime.h>
#include <math.h>

#define NN 2048
#define MM 128
#define KD 8
#define K2 64
#define NPACK 36
#define NPB 8             // children per block in pair kernel
#define NB (NN / NPB)     // 256 chunks per t -> grid (256,2)=512 blocks, 1 wave
#define FULLM 0xffffffffu

// ---------------- scratch --------------------------------------------------
__device__ float4 g_C4[2][11][MM];     // 44 coefs per m: 36 Bp + 8 (-h), SoA over m
__device__ float  g_dm[2][MM];         // -log|det O| + 0.5 logdetS - 4 + 0.5 ee
__device__ float  g_child[2][NN][48];  // [36 Atilde pk][8 v][c'][3 pad]
__device__ double g_part[2][NB];
__device__ unsigned int g_done;

// ---------------- f32x2 helpers --------------------------------------------
__device__ __forceinline__ void ffma2(unsigned long long& d,
                                      unsigned long long a, unsigned long long b) {
    asm("fma.rn.f32x2 %0, %1, %2, %0;" : "+l"(d) : "l"(a), "l"(b));
}
__device__ __forceinline__ float2 unpack2(unsigned long long v) {
    float2 f;
    asm("mov.b64 {%0, %1}, %2;" : "=f"(f.x), "=f"(f.y) : "l"(v));
    return f;
}

// ==================== parent work (proven R4/R8 serial chain) =================
__device__ void parent_work(int t, int m, const float* __restrict__ mup,
                            const float* __restrict__ Sp,
                            const float* __restrict__ Op) {
    float __align__(16) S[KD][KD];
    float __align__(16) O[KD][KD];
    float __align__(16) e[KD];
    {
        const float4* s4 = reinterpret_cast<const float4*>(Sp + (size_t)m * K2);
        const float4* o4 = reinterpret_cast<const float4*>(Op + (size_t)m * K2);
        float4* Sd = reinterpret_cast<float4*>(&S[0][0]);
        float4* Od = reinterpret_cast<float4*>(&O[0][0]);
#pragma unroll
        for (int q = 0; q < 16; q++) { Sd[q] = s4[q]; Od[q] = o4[q]; }
        const float4* m4 = reinterpret_cast<const float4*>(mup + (size_t)m * KD);
        reinterpret_cast<float4*>(e)[0] = m4[0];
        reinterpret_cast<float4*>(e)[1] = m4[1];
    }
    // Cholesky in place (lower triangle -> L)
#pragma unroll
    for (int j = 0; j < KD; j++) {
        float s = S[j][j];
#pragma unroll
        for (int k = 0; k < j; k++) s -= S[j][k] * S[j][k];
        float ljj = sqrtf(s);
        S[j][j] = ljj;
        float inv = 1.f / ljj;
#pragma unroll
        for (int i = j + 1; i < KD; i++) {
            float si = S[i][j];
#pragma unroll
            for (int k = 0; k < j; k++) si -= S[i][k] * S[j][k];
            S[i][j] = si * inv;
        }
    }
    // G = L^{-1} O in place, e := L^{-1} e
#pragma unroll
    for (int i = 0; i < KD; i++) {
        float inv = 1.f / S[i][i];
#pragma unroll
        for (int c = 0; c < KD; c++) {
            float s = O[i][c];
#pragma unroll
            for (int k = 0; k < i; k++) s -= S[i][k] * O[k][c];
            O[i][c] = s * inv;
        }
        float se = e[i];
#pragma unroll
        for (int k = 0; k < i; k++) se -= S[i][k] * e[k];
        e[i] = se * inv;
    }
    float cf[44];
    {
        int p = 0;
#pragma unroll
        for (int i = 0; i < KD; i++) {
#pragma unroll
            for (int j = i; j < KD; j++) {
                float b = 0.f;
#pragma unroll
                for (int k = 0; k < KD; k++) b += O[k][i] * O[k][j];
                cf[p++] = (i == j) ? 0.5f * b : b;
            }
        }
    }
    float ee = 0.f;
#pragma unroll
    for (int i = 0; i < KD; i++) {
        float s = 0.f;
#pragma unroll
        for (int k = 0; k < KD; k++) s += O[k][i] * e[k];
        cf[NPACK + i] = -s;
        ee += e[i] * e[i];
    }
#pragma unroll
    for (int q = 0; q < 11; q++)
        g_C4[t][q][m] = make_float4(cf[4 * q], cf[4 * q + 1], cf[4 * q + 2], cf[4 * q + 3]);
    float pd = 1.f;
#pragma unroll
    for (int j = 0; j < KD; j++) {
        float piv = O[j][j];
        pd *= piv;
        float ip = 1.f / piv;
#pragma unroll
        for (int r = j + 1; r < KD; r++) {
            float f = O[r][j] * ip;
#pragma unroll
            for (int c = j + 1; c < KD; c++) O[r][c] -= f * O[j][c];
        }
    }
    g_dm[t][m] = -logf(fabsf(pd)) - 4.0f + 0.5f * ee;
}

// ==================== child work (proven R4/R8 serial chain) ==================
__device__ void child_work(int t, int n, const float* __restrict__ muc,
                           const float* __restrict__ Sc,
                           const float* __restrict__ Oc) {
    float __align__(16) O[KD][KD];
    float __align__(16) S[KD][KD];
    float __align__(16) mu[KD];
    {
        const float4* s4 = reinterpret_cast<const float4*>(Sc + (size_t)n * K2);
        const float4* o4 = reinterpret_cast<const float4*>(Oc + (size_t)n * K2);
        float4* Sd = reinterpret_cast<float4*>(&S[0][0]);
        float4* Od = reinterpret_cast<float4*>(&O[0][0]);
#pragma unroll
        for (int q = 0; q < 16; q++) { Sd[q] = s4[q]; Od[q] = o4[q]; }
        const float4* m4 = reinterpret_cast<const float4*>(muc + (size_t)n * KD);
        reinterpret_cast<float4*>(mu)[0] = m4[0];
        reinterpret_cast<float4*>(mu)[1] = m4[1];
    }
    float pd = 1.f;
#pragma unroll
    for (int k = 0; k < KD; k++) {
        float piv = O[k][k];
        pd *= piv;
        float ip = 1.f / piv;
#pragma unroll
        for (int i = 0; i < KD; i++) {
            if (i == k) continue;
            float f = O[i][k] * ip;
#pragma unroll
            for (int j = 0; j < KD; j++)
                if (j != k) O[i][j] -= f * O[k][j];
            O[i][k] = -f;
        }
#pragma unroll
        for (int j = 0; j < KD; j++)
            if (j != k) O[k][j] *= ip;
        O[k][k] = ip;
    }
    float lad = logf(fabsf(pd));

    float out[45];
    float v[KD];
#pragma unroll
    for (int i = 0; i < KD; i++) {
        float s = 0.f;
#pragma unroll
        for (int j = 0; j < KD; j++) s += O[i][j] * mu[j];
        v[i] = s;
        out[NPACK + i] = s;
    }
    {
        int p = 0;
#pragma unroll
        for (int i = 0; i < KD; i++) {
            float trow[KD];
#pragma unroll
            for (int c = 0; c < KD; c++) {
                float s = 0.f;
#pragma unroll
                for (int b = 0; b < KD; b++) s += O[i][b] * S[b][c];
                trow[c] = s;
            }
#pragma unroll
            for (int j = i; j < KD; j++) {
                float a = v[i] * v[j];
#pragma unroll
                for (int c = 0; c < KD; c++) a += trow[c] * O[j][c];
                out[p++] = a;
            }
        }
    }
    float pl = 1.f;
#pragma unroll
    for (int j = 0; j < KD; j++) {
        float s = S[j][j];
#pragma unroll
        for (int k = 0; k < j; k++) s -= S[j][k] * S[j][k];
        float ljj = sqrtf(s);
        S[j][j] = ljj;
        pl *= ljj;
        float inv = 1.f / ljj;
#pragma unroll
        for (int i = j + 1; i < KD; i++) {
            float si = S[i][j];
#pragma unroll
            for (int k = 0; k < j; k++) si -= S[i][k] * S[j][k];
            S[i][j] = si * inv;
        }
    }
    float4* dst = reinterpret_cast<float4*>(&g_child[t][n][0]);
#pragma unroll
    for (int q = 0; q < 11; q++)
        dst[q] = make_float4(out[4 * q], out[4 * q + 1], out[4 * q + 2], out[4 * q + 3]);
    g_child[t][n][44] = lad - logf(pl);
}

// ==================== precompute kernel (R8 proven) ===========================
__global__ __launch_bounds__(32)
void precompute_kernel(const float* __restrict__ mu_p, const float* __restrict__ sigma_p,
                       const float* __restrict__ omega_child,
                       const float* __restrict__ mu_q, const float* __restrict__ sigma_q,
                       const float* __restrict__ omega_parent,
                       const float* __restrict__ mu_r, const float* __restrict__ sigma_r,
                       const float* __restrict__ omega_m_child,
                       const float* __restrict__ mu_s, const float* __restrict__ sigma_s,
                       const float* __restrict__ omega_m_parent) {
    int bid = blockIdx.x;
    int tid = threadIdx.x;
    if (bid == 0 && tid == 0) g_done = 0u;
    if (bid < 8) {
        int gid = bid * 32 + tid;   // 256 = 2 t x 128 m
        int t = gid >> 7;
        int m = gid & (MM - 1);
        if (t == 0) parent_work(0, m, mu_q, sigma_q, omega_parent);
        else        parent_work(1, m, mu_s, sigma_s, omega_m_parent);
    } else {
        int gid = (bid - 8) * 32 + tid;  // 4096 = 2 t x 2048 n
        int t = gid >> 11;
        int n = gid & (NN - 1);
        if (t == 0) child_work(0, n, mu_p, sigma_p, omega_child);
        else        child_work(1, n, mu_r, sigma_r, omega_m_child);
    }
}

// ==================== pair kernel (R8 + NPB=8 single wave) ====================
__global__ __launch_bounds__(128)
void pair_kernel(const float* __restrict__ W, float* __restrict__ out) {
    const int t = blockIdx.y;
    const int m = threadIdx.x;
    const int n0 = blockIdx.x * NPB;

    // W prefetch first (DRAM): 8 coalesced LDG.32
    float wv[NPB];
#pragma unroll
    for (int k = 0; k < NPB; k++) wv[k] = W[(n0 + k) * MM + m];

    // coef prologue: 11 coalesced LDG.128 + dm (L2)
    float4 c4[11];
#pragma unroll
    for (int q = 0; q < 11; q++) c4[q] = g_C4[t][q][m];
    const float dm = g_dm[t][m];
    const unsigned long long* c2 = reinterpret_cast<const unsigned long long*>(c4);

    // stage 8 child records into shared (96 float4, coalesced)
    __shared__ __align__(16) float4 sh4[NPB * 12];
    if (m < NPB * 12) {
        int k = m / 12, rr = m % 12;
        sh4[m] = reinterpret_cast<const float4*>(&g_child[t][n0 + k][0])[rr];
    }
    __syncthreads();

    float accf = 0.f;
#pragma unroll
    for (int k = 0; k < NPB; k++) {
        const unsigned long long* a2 =
            reinterpret_cast<const unsigned long long*>(&sh4[k * 12]);
        unsigned long long acc0 = 0ull, acc1 = 0ull;
#pragma unroll
        for (int p = 0; p < 22; p += 2) {
            ffma2(acc0, c2[p], a2[p]);
            ffma2(acc1, c2[p + 1], a2[p + 1]);
        }
        float2 s0 = unpack2(acc0);
        float2 s1 = unpack2(acc1);
        float cc = reinterpret_cast<const float*>(&sh4[k * 12])[44];
        float kl = (s0.x + s0.y) + (s1.x + s1.y) + (dm + cc);
        accf = fmaf(wv[k], kl, accf);
    }

    // fp32 warp reduce -> fp64 block partial, ticket finalize
#pragma unroll
    for (int off = 16; off; off >>= 1)
        accf += __shfl_down_sync(FULLM, accf, off);
    __shared__ float wsumf[4];
    __shared__ int islast;
    if ((m & 31) == 0) wsumf[m >> 5] = accf;
    __syncthreads();
    if (m == 0) {
        g_part[t][blockIdx.x] =
            (double)wsumf[0] + (double)wsumf[1] + (double)wsumf[2] + (double)wsumf[3];
        __threadfence();
        unsigned int tick = atomicAdd(&g_done, 1u);
        islast = (tick == 2u * NB - 1u) ? 1 : 0;
    }
    __syncthreads();
    if (islast) {
        __threadfence();
        double s0 = g_part[0][m] + g_part[0][m + 128];
        double s1 = g_part[1][m] + g_part[1][m + 128];
#pragma unroll
        for (int off = 16; off; off >>= 1) {
            s0 += __shfl_down_sync(FULLM, s0, off);
            s1 += __shfl_down_sync(FULLM, s1, off);
        }
        __shared__ double ws0[4], ws1[4];
        if ((m & 31) == 0) { ws0[m >> 5] = s0; ws1[m >> 5] = s1; }
        __syncthreads();
        if (m == 0) {
            double b  = ws0[0] + ws0[1] + ws0[2] + ws0[3];
            double mo = ws1[0] + ws1[1] + ws1[2] + ws1[3];
            out[0] = (float)(b + mo);
            out[1] = (float)b;
            out[2] = (float)mo;
        }
    }
}

// ----------------------------------------------------------------------------
extern "C" void kernel_launch(void* const* d_in, const int* in_sizes, int n_in,
                              void* d_out, int out_size) {
    const float* W              = (const float*)d_in[0];
    const float* mu_p           = (const float*)d_in[1];
    const float* sigma_p        = (const float*)d_in[2];
    const float* mu_q_parent    = (const float*)d_in[3];
    const float* sigma_q_parent = (const float*)d_in[4];
    const float* omega_child    = (const float*)d_in[5];
    const float* omega_parent   = (const float*)d_in[6];
    const float* mu_r           = (const float*)d_in[7];
    const float* sigma_r        = (const float*)d_in[8];
    const float* mu_s_parent    = (const float*)d_in[9];
    const float* sigma_s_parent = (const float*)d_in[10];
    const float* omega_m_child  = (const float*)d_in[11];
    const float* omega_m_parent = (const float*)d_in[12];

    precompute_kernel<<<136, 32>>>(mu_p, sigma_p, omega_child,
                                   mu_q_parent, sigma_q_parent, omega_parent,
                                   mu_r, sigma_r, omega_m_child,
                                   mu_s_parent, sigma_s_parent, omega_m_parent);
    pair_kernel<<<dim3(NB, 2), MM>>>(W, (float*)d_out);
}

// round 16
// speedup vs baseline: 4.0861x; 1.0450x over previous
#include <cuda_runtime.h>
#include <math.h>

#define NN 2048
#define MM 128
#define KD 8
#define K2 64
#define NPACK 36
#define NPB 8             // children per block in pair kernel
#define NB (NN / NPB)     // 256 chunks per t -> grid (256,2)=512 blocks, 1 wave
#define FULLM 0xffffffffu

// ---------------- scratch --------------------------------------------------
__device__ float4 g_C4[2][11][MM];     // 44 coefs per m: 36 Bp + 8 (-h), SoA over m
__device__ float  g_dm[2][MM];         // -log|det O| + 0.5 logdetS - 4 + 0.5 ee
__device__ float  g_child[2][NN][48];  // [36 Atilde pk][8 v][c'][3 pad]
__device__ double g_part[2][NB];
__device__ unsigned int g_done;

// ---------------- f32x2 helpers --------------------------------------------
__device__ __forceinline__ void ffma2(unsigned long long& d,
                                      unsigned long long a, unsigned long long b) {
    asm("fma.rn.f32x2 %0, %1, %2, %0;" : "+l"(d) : "l"(a), "l"(b));
}
__device__ __forceinline__ float2 unpack2(unsigned long long v) {
    float2 f;
    asm("mov.b64 {%0, %1}, %2;" : "=f"(f.x), "=f"(f.y) : "l"(v));
    return f;
}

// ==================== parent work (proven R4/R8 serial chain) =================
__device__ void parent_work(int t, int m, const float* __restrict__ mup,
                            const float* __restrict__ Sp,
                            const float* __restrict__ Op) {
    float __align__(16) S[KD][KD];
    float __align__(16) O[KD][KD];
    float __align__(16) e[KD];
    {
        const float4* s4 = reinterpret_cast<const float4*>(Sp + (size_t)m * K2);
        const float4* o4 = reinterpret_cast<const float4*>(Op + (size_t)m * K2);
        float4* Sd = reinterpret_cast<float4*>(&S[0][0]);
        float4* Od = reinterpret_cast<float4*>(&O[0][0]);
#pragma unroll
        for (int q = 0; q < 16; q++) { Sd[q] = s4[q]; Od[q] = o4[q]; }
        const float4* m4 = reinterpret_cast<const float4*>(mup + (size_t)m * KD);
        reinterpret_cast<float4*>(e)[0] = m4[0];
        reinterpret_cast<float4*>(e)[1] = m4[1];
    }
    // Cholesky in place (lower triangle -> L)
#pragma unroll
    for (int j = 0; j < KD; j++) {
        float s = S[j][j];
#pragma unroll
        for (int k = 0; k < j; k++) s -= S[j][k] * S[j][k];
        float ljj = sqrtf(s);
        S[j][j] = ljj;
        float inv = 1.f / ljj;
#pragma unroll
        for (int i = j + 1; i < KD; i++) {
            float si = S[i][j];
#pragma unroll
            for (int k = 0; k < j; k++) si -= S[i][k] * S[j][k];
            S[i][j] = si * inv;
        }
    }
    // G = L^{-1} O in place, e := L^{-1} e
#pragma unroll
    for (int i = 0; i < KD; i++) {
        float inv = 1.f / S[i][i];
#pragma unroll
        for (int c = 0; c < KD; c++) {
            float s = O[i][c];
#pragma unroll
            for (int k = 0; k < i; k++) s -= S[i][k] * O[k][c];
            O[i][c] = s * inv;
        }
        float se = e[i];
#pragma unroll
        for (int k = 0; k < i; k++) se -= S[i][k] * e[k];
        e[i] = se * inv;
    }
    float cf[44];
    {
        int p = 0;
#pragma unroll
        for (int i = 0; i < KD; i++) {
#pragma unroll
            for (int j = i; j < KD; j++) {
                float b = 0.f;
#pragma unroll
                for (int k = 0; k < KD; k++) b += O[k][i] * O[k][j];
                cf[p++] = (i == j) ? 0.5f * b : b;
            }
        }
    }
    float ee = 0.f;
#pragma unroll
    for (int i = 0; i < KD; i++) {
        float s = 0.f;
#pragma unroll
        for (int k = 0; k < KD; k++) s += O[k][i] * e[k];
        cf[NPACK + i] = -s;
        ee += e[i] * e[i];
    }
#pragma unroll
    for (int q = 0; q < 11; q++)
        g_C4[t][q][m] = make_float4(cf[4 * q], cf[4 * q + 1], cf[4 * q + 2], cf[4 * q + 3]);
    float pd = 1.f;
#pragma unroll
    for (int j = 0; j < KD; j++) {
        float piv = O[j][j];
        pd *= piv;
        float ip = 1.f / piv;
#pragma unroll
        for (int r = j + 1; r < KD; r++) {
            float f = O[r][j] * ip;
#pragma unroll
            for (int c = j + 1; c < KD; c++) O[r][c] -= f * O[j][c];
        }
    }
    g_dm[t][m] = -logf(fabsf(pd)) - 4.0f + 0.5f * ee;
}

// ==================== child work (proven R4/R8 serial chain) ==================
__device__ void child_work(int t, int n, const float* __restrict__ muc,
                           const float* __restrict__ Sc,
                           const float* __restrict__ Oc) {
    float __align__(16) O[KD][KD];
    float __align__(16) S[KD][KD];
    float __align__(16) mu[KD];
    {
        const float4* s4 = reinterpret_cast<const float4*>(Sc + (size_t)n * K2);
        const float4* o4 = reinterpret_cast<const float4*>(Oc + (size_t)n * K2);
        float4* Sd = reinterpret_cast<float4*>(&S[0][0]);
        float4* Od = reinterpret_cast<float4*>(&O[0][0]);
#pragma unroll
        for (int q = 0; q < 16; q++) { Sd[q] = s4[q]; Od[q] = o4[q]; }
        const float4* m4 = reinterpret_cast<const float4*>(muc + (size_t)n * KD);
        reinterpret_cast<float4*>(mu)[0] = m4[0];
        reinterpret_cast<float4*>(mu)[1] = m4[1];
    }
    float pd = 1.f;
#pragma unroll
    for (int k = 0; k < KD; k++) {
        float piv = O[k][k];
        pd *= piv;
        float ip = 1.f / piv;
#pragma unroll
        for (int i = 0; i < KD; i++) {
            if (i == k) continue;
            float f = O[i][k] * ip;
#pragma unroll
            for (int j = 0; j < KD; j++)
                if (j != k) O[i][j] -= f * O[k][j];
            O[i][k] = -f;
        }
#pragma unroll
        for (int j = 0; j < KD; j++)
            if (j != k) O[k][j] *= ip;
        O[k][k] = ip;
    }
    float lad = logf(fabsf(pd));

    float out[45];
    float v[KD];
#pragma unroll
    for (int i = 0; i < KD; i++) {
        float s = 0.f;
#pragma unroll
        for (int j = 0; j < KD; j++) s += O[i][j] * mu[j];
        v[i] = s;
        out[NPACK + i] = s;
    }
    {
        int p = 0;
#pragma unroll
        for (int i = 0; i < KD; i++) {
            float trow[KD];
#pragma unroll
            for (int c = 0; c < KD; c++) {
                float s = 0.f;
#pragma unroll
                for (int b = 0; b < KD; b++) s += O[i][b] * S[b][c];
                trow[c] = s;
            }
#pragma unroll
            for (int j = i; j < KD; j++) {
                float a = v[i] * v[j];
#pragma unroll
                for (int c = 0; c < KD; c++) a += trow[c] * O[j][c];
                out[p++] = a;
            }
        }
    }
    float pl = 1.f;
#pragma unroll
    for (int j = 0; j < KD; j++) {
        float s = S[j][j];
#pragma unroll
        for (int k = 0; k < j; k++) s -= S[j][k] * S[j][k];
        float ljj = sqrtf(s);
        S[j][j] = ljj;
        pl *= ljj;
        float inv = 1.f / ljj;
#pragma unroll
        for (int i = j + 1; i < KD; i++) {
            float si = S[i][j];
#pragma unroll
            for (int k = 0; k < j; k++) si -= S[i][k] * S[j][k];
            S[i][j] = si * inv;
        }
    }
    float4* dst = reinterpret_cast<float4*>(&g_child[t][n][0]);
#pragma unroll
    for (int q = 0; q < 11; q++)
        dst[q] = make_float4(out[4 * q], out[4 * q + 1], out[4 * q + 2], out[4 * q + 3]);
    g_child[t][n][44] = lad - logf(pl);
}

// ==================== precompute kernel (R8 proven) ===========================
__global__ __launch_bounds__(32)
void precompute_kernel(const float* __restrict__ mu_p, const float* __restrict__ sigma_p,
                       const float* __restrict__ omega_child,
                       const float* __restrict__ mu_q, const float* __restrict__ sigma_q,
                       const float* __restrict__ omega_parent,
                       const float* __restrict__ mu_r, const float* __restrict__ sigma_r,
                       const float* __restrict__ omega_m_child,
                       const float* __restrict__ mu_s, const float* __restrict__ sigma_s,
                       const float* __restrict__ omega_m_parent) {
    int bid = blockIdx.x;
    int tid = threadIdx.x;
    if (bid == 0 && tid == 0) g_done = 0u;
    if (bid < 8) {
        int gid = bid * 32 + tid;   // 256 = 2 t x 128 m
        int t = gid >> 7;
        int m = gid & (MM - 1);
        if (t == 0) parent_work(0, m, mu_q, sigma_q, omega_parent);
        else        parent_work(1, m, mu_s, sigma_s, omega_m_parent);
    } else {
        int gid = (bid - 8) * 32 + tid;  // 4096 = 2 t x 2048 n
        int t = gid >> 11;
        int n = gid & (NN - 1);
        if (t == 0) child_work(0, n, mu_p, sigma_p, omega_child);
        else        child_work(1, n, mu_r, sigma_r, omega_m_child);
    }
}

// ==================== pair kernel (R8 + NPB=8 single wave) ====================
__global__ __launch_bounds__(128)
void pair_kernel(const float* __restrict__ W, float* __restrict__ out) {
    const int t = blockIdx.y;
    const int m = threadIdx.x;
    const int n0 = blockIdx.x * NPB;

    // W prefetch first (DRAM): 8 coalesced LDG.32
    float wv[NPB];
#pragma unroll
    for (int k = 0; k < NPB; k++) wv[k] = W[(n0 + k) * MM + m];

    // coef prologue: 11 coalesced LDG.128 + dm (L2)
    float4 c4[11];
#pragma unroll
    for (int q = 0; q < 11; q++) c4[q] = g_C4[t][q][m];
    const float dm = g_dm[t][m];
    const unsigned long long* c2 = reinterpret_cast<const unsigned long long*>(c4);

    // stage 8 child records into shared (96 float4, coalesced)
    __shared__ __align__(16) float4 sh4[NPB * 12];
    if (m < NPB * 12) {
        int k = m / 12, rr = m % 12;
        sh4[m] = reinterpret_cast<const float4*>(&g_child[t][n0 + k][0])[rr];
    }
    __syncthreads();

    float accf = 0.f;
#pragma unroll
    for (int k = 0; k < NPB; k++) {
        const unsigned long long* a2 =
            reinterpret_cast<const unsigned long long*>(&sh4[k * 12]);
        unsigned long long acc0 = 0ull, acc1 = 0ull;
#pragma unroll
        for (int p = 0; p < 22; p += 2) {
            ffma2(acc0, c2[p], a2[p]);
            ffma2(acc1, c2[p + 1], a2[p + 1]);
        }
        float2 s0 = unpack2(acc0);
        float2 s1 = unpack2(acc1);
        float cc = reinterpret_cast<const float*>(&sh4[k * 12])[44];
        float kl = (s0.x + s0.y) + (s1.x + s1.y) + (dm + cc);
        accf = fmaf(wv[k], kl, accf);
    }

    // fp32 warp reduce -> fp64 block partial, ticket finalize
#pragma unroll
    for (int off = 16; off; off >>= 1)
        accf += __shfl_down_sync(FULLM, accf, off);
    __shared__ float wsumf[4];
    __shared__ int islast;
    if ((m & 31) == 0) wsumf[m >> 5] = accf;
    __syncthreads();
    if (m == 0) {
        g_part[t][blockIdx.x] =
            (double)wsumf[0] + (double)wsumf[1] + (double)wsumf[2] + (double)wsumf[3];
        __threadfence();
        unsigned int tick = atomicAdd(&g_done, 1u);
        islast = (tick == 2u * NB - 1u) ? 1 : 0;
    }
    __syncthreads();
    if (islast) {
        __threadfence();
        double s0 = g_part[0][m] + g_part[0][m + 128];
        double s1 = g_part[1][m] + g_part[1][m + 128];
#pragma unroll
        for (int off = 16; off; off >>= 1) {
            s0 += __shfl_down_sync(FULLM, s0, off);
            s1 += __shfl_down_sync(FULLM, s1, off);
        }
        __shared__ double ws0[4], ws1[4];
        if ((m & 31) == 0) { ws0[m >> 5] = s0; ws1[m >> 5] = s1; }
        __syncthreads();
        if (m == 0) {
            double b  = ws0[0] + ws0[1] + ws0[2] + ws0[3];
            double mo = ws1[0] + ws1[1] + ws1[2] + ws1[3];
            out[0] = (float)(b + mo);
            out[1] = (float)b;
            out[2] = (float)mo;
        }
    }
}

// ----------------------------------------------------------------------------
extern "C" void kernel_launch(void* const* d_in, const int* in_sizes, int n_in,
                              void* d_out, int out_size) {
    const float* W              = (const float*)d_in[0];
    const float* mu_p           = (const float*)d_in[1];
    const float* sigma_p        = (const float*)d_in[2];
    const float* mu_q_parent    = (const float*)d_in[3];
    const float* sigma_q_parent = (const float*)d_in[4];
    const float* omega_child    = (const float*)d_in[5];
    const float* omega_parent   = (const float*)d_in[6];
    const float* mu_r           = (const float*)d_in[7];
    const float* sigma_r        = (const float*)d_in[8];
    const float* mu_s_parent    = (const float*)d_in[9];
    const float* sigma_s_parent = (const float*)d_in[10];
    const float* omega_m_child  = (const float*)d_in[11];
    const float* omega_m_parent = (const float*)d_in[12];

    precompute_kernel<<<136, 32>>>(mu_p, sigma_p, omega_child,
                                   mu_q_parent, sigma_q_parent, omega_parent,
                                   mu_r, sigma_r, omega_m_child,
                                   mu_s_parent, sigma_s_parent, omega_m_parent);
    pair_kernel<<<dim3(NB, 2), MM>>>(W, (float*)d_out);
}

// round 17
// speedup vs baseline: 4.5000x; 1.1013x over previous
#include <cuda_runtime.h>
#include <math.h>

#define NN 2048
#define MM 128
#define KD 8
#define K2 64
#define NPACK 36
#define NPB 8             // children per block in pair kernel
#define NB (NN / NPB)     // 256 chunks per t -> grid (256,2)=512 blocks, 1 wave
#define FULLM 0xffffffffu

// ---------------- scratch --------------------------------------------------
__device__ float4 g_C4[2][11][MM];     // 44 coefs per m: 36 Bp + 8 (-h), SoA over m
__device__ float  g_dm[2][MM];         // -log|det O| + 0.5 logdetS - 4 + 0.5 ee
__device__ float  g_child[2][NN][48];  // [36 Atilde pk][8 v][c'][3 pad]
__device__ double g_part[2][NB];
__device__ unsigned int g_done;

// ---------------- f32x2 helpers --------------------------------------------
__device__ __forceinline__ void ffma2(unsigned long long& d,
                                      unsigned long long a, unsigned long long b) {
    asm("fma.rn.f32x2 %0, %1, %2, %0;" : "+l"(d) : "l"(a), "l"(b));
}
__device__ __forceinline__ float2 unpack2(unsigned long long v) {
    float2 f;
    asm("mov.b64 {%0, %1}, %2;" : "=f"(f.x), "=f"(f.y) : "l"(v));
    return f;
}

// ==================== parent work (proven R4/R8 serial chain) =================
__device__ void parent_work(int t, int m, const float* __restrict__ mup,
                            const float* __restrict__ Sp,
                            const float* __restrict__ Op) {
    float __align__(16) S[KD][KD];
    float __align__(16) O[KD][KD];
    float __align__(16) e[KD];
    {
        const float4* s4 = reinterpret_cast<const float4*>(Sp + (size_t)m * K2);
        const float4* o4 = reinterpret_cast<const float4*>(Op + (size_t)m * K2);
        float4* Sd = reinterpret_cast<float4*>(&S[0][0]);
        float4* Od = reinterpret_cast<float4*>(&O[0][0]);
#pragma unroll
        for (int q = 0; q < 16; q++) { Sd[q] = s4[q]; Od[q] = o4[q]; }
        const float4* m4 = reinterpret_cast<const float4*>(mup + (size_t)m * KD);
        reinterpret_cast<float4*>(e)[0] = m4[0];
        reinterpret_cast<float4*>(e)[1] = m4[1];
    }
    // Cholesky in place (lower triangle -> L)
#pragma unroll
    for (int j = 0; j < KD; j++) {
        float s = S[j][j];
#pragma unroll
        for (int k = 0; k < j; k++) s -= S[j][k] * S[j][k];
        float ljj = sqrtf(s);
        S[j][j] = ljj;
        float inv = 1.f / ljj;
#pragma unroll
        for (int i = j + 1; i < KD; i++) {
            float si = S[i][j];
#pragma unroll
            for (int k = 0; k < j; k++) si -= S[i][k] * S[j][k];
            S[i][j] = si * inv;
        }
    }
    // G = L^{-1} O in place, e := L^{-1} e
#pragma unroll
    for (int i = 0; i < KD; i++) {
        float inv = 1.f / S[i][i];
#pragma unroll
        for (int c = 0; c < KD; c++) {
            float s = O[i][c];
#pragma unroll
            for (int k = 0; k < i; k++) s -= S[i][k] * O[k][c];
            O[i][c] = s * inv;
        }
        float se = e[i];
#pragma unroll
        for (int k = 0; k < i; k++) se -= S[i][k] * e[k];
        e[i] = se * inv;
    }
    float cf[44];
    {
        int p = 0;
#pragma unroll
        for (int i = 0; i < KD; i++) {
#pragma unroll
            for (int j = i; j < KD; j++) {
                float b = 0.f;
#pragma unroll
                for (int k = 0; k < KD; k++) b += O[k][i] * O[k][j];
                cf[p++] = (i == j) ? 0.5f * b : b;
            }
        }
    }
    float ee = 0.f;
#pragma unroll
    for (int i = 0; i < KD; i++) {
        float s = 0.f;
#pragma unroll
        for (int k = 0; k < KD; k++) s += O[k][i] * e[k];
        cf[NPACK + i] = -s;
        ee += e[i] * e[i];
    }
#pragma unroll
    for (int q = 0; q < 11; q++)
        g_C4[t][q][m] = make_float4(cf[4 * q], cf[4 * q + 1], cf[4 * q + 2], cf[4 * q + 3]);
    float pd = 1.f;
#pragma unroll
    for (int j = 0; j < KD; j++) {
        float piv = O[j][j];
        pd *= piv;
        float ip = 1.f / piv;
#pragma unroll
        for (int r = j + 1; r < KD; r++) {
            float f = O[r][j] * ip;
#pragma unroll
            for (int c = j + 1; c < KD; c++) O[r][c] -= f * O[j][c];
        }
    }
    g_dm[t][m] = -logf(fabsf(pd)) - 4.0f + 0.5f * ee;
}

// ==================== child work (proven R4/R8 serial chain) ==================
__device__ void child_work(int t, int n, const float* __restrict__ muc,
                           const float* __restrict__ Sc,
                           const float* __restrict__ Oc) {
    float __align__(16) O[KD][KD];
    float __align__(16) S[KD][KD];
    float __align__(16) mu[KD];
    {
        const float4* s4 = reinterpret_cast<const float4*>(Sc + (size_t)n * K2);
        const float4* o4 = reinterpret_cast<const float4*>(Oc + (size_t)n * K2);
        float4* Sd = reinterpret_cast<float4*>(&S[0][0]);
        float4* Od = reinterpret_cast<float4*>(&O[0][0]);
#pragma unroll
        for (int q = 0; q < 16; q++) { Sd[q] = s4[q]; Od[q] = o4[q]; }
        const float4* m4 = reinterpret_cast<const float4*>(muc + (size_t)n * KD);
        reinterpret_cast<float4*>(mu)[0] = m4[0];
        reinterpret_cast<float4*>(mu)[1] = m4[1];
    }
    float pd = 1.f;
#pragma unroll
    for (int k = 0; k < KD; k++) {
        float piv = O[k][k];
        pd *= piv;
        float ip = 1.f / piv;
#pragma unroll
        for (int i = 0; i < KD; i++) {
            if (i == k) continue;
            float f = O[i][k] * ip;
#pragma unroll
            for (int j = 0; j < KD; j++)
                if (j != k) O[i][j] -= f * O[k][j];
            O[i][k] = -f;
        }
#pragma unroll
        for (int j = 0; j < KD; j++)
            if (j != k) O[k][j] *= ip;
        O[k][k] = ip;
    }
    float lad = logf(fabsf(pd));

    float out[45];
    float v[KD];
#pragma unroll
    for (int i = 0; i < KD; i++) {
        float s = 0.f;
#pragma unroll
        for (int j = 0; j < KD; j++) s += O[i][j] * mu[j];
        v[i] = s;
        out[NPACK + i] = s;
    }
    {
        int p = 0;
#pragma unroll
        for (int i = 0; i < KD; i++) {
            float trow[KD];
#pragma unroll
            for (int c = 0; c < KD; c++) {
                float s = 0.f;
#pragma unroll
                for (int b = 0; b < KD; b++) s += O[i][b] * S[b][c];
                trow[c] = s;
            }
#pragma unroll
            for (int j = i; j < KD; j++) {
                float a = v[i] * v[j];
#pragma unroll
                for (int c = 0; c < KD; c++) a += trow[c] * O[j][c];
                out[p++] = a;
            }
        }
    }
    float pl = 1.f;
#pragma unroll
    for (int j = 0; j < KD; j++) {
        float s = S[j][j];
#pragma unroll
        for (int k = 0; k < j; k++) s -= S[j][k] * S[j][k];
        float ljj = sqrtf(s);
        S[j][j] = ljj;
        pl *= ljj;
        float inv = 1.f / ljj;
#pragma unroll
        for (int i = j + 1; i < KD; i++) {
            float si = S[i][j];
#pragma unroll
            for (int k = 0; k < j; k++) si -= S[i][k] * S[j][k];
            S[i][j] = si * inv;
        }
    }
    float4* dst = reinterpret_cast<float4*>(&g_child[t][n][0]);
#pragma unroll
    for (int q = 0; q < 11; q++)
        dst[q] = make_float4(out[4 * q], out[4 * q + 1], out[4 * q + 2], out[4 * q + 3]);
    g_child[t][n][44] = lad - logf(pl);
}

// ==================== precompute kernel (R8 proven) ===========================
__global__ __launch_bounds__(32)
void precompute_kernel(const float* __restrict__ mu_p, const float* __restrict__ sigma_p,
                       const float* __restrict__ omega_child,
                       const float* __restrict__ mu_q, const float* __restrict__ sigma_q,
                       const float* __restrict__ omega_parent,
                       const float* __restrict__ mu_r, const float* __restrict__ sigma_r,
                       const float* __restrict__ omega_m_child,
                       const float* __restrict__ mu_s, const float* __restrict__ sigma_s,
                       const float* __restrict__ omega_m_parent) {
    int bid = blockIdx.x;
    int tid = threadIdx.x;
    if (bid == 0 && tid == 0) g_done = 0u;
    if (bid < 8) {
        int gid = bid * 32 + tid;   // 256 = 2 t x 128 m
        int t = gid >> 7;
        int m = gid & (MM - 1);
        if (t == 0) parent_work(0, m, mu_q, sigma_q, omega_parent);
        else        parent_work(1, m, mu_s, sigma_s, omega_m_parent);
    } else {
        int gid = (bid - 8) * 32 + tid;  // 4096 = 2 t x 2048 n
        int t = gid >> 11;
        int n = gid & (NN - 1);
        if (t == 0) child_work(0, n, mu_p, sigma_p, omega_child);
        else        child_work(1, n, mu_r, sigma_r, omega_m_child);
    }
}

// ==================== pair kernel (R8 + NPB=8 single wave) ====================
__global__ __launch_bounds__(128)
void pair_kernel(const float* __restrict__ W, float* __restrict__ out) {
    const int t = blockIdx.y;
    const int m = threadIdx.x;
    const int n0 = blockIdx.x * NPB;

    // W prefetch first (DRAM): 8 coalesced LDG.32
    float wv[NPB];
#pragma unroll
    for (int k = 0; k < NPB; k++) wv[k] = W[(n0 + k) * MM + m];

    // coef prologue: 11 coalesced LDG.128 + dm (L2)
    float4 c4[11];
#pragma unroll
    for (int q = 0; q < 11; q++) c4[q] = g_C4[t][q][m];
    const float dm = g_dm[t][m];
    const unsigned long long* c2 = reinterpret_cast<const unsigned long long*>(c4);

    // stage 8 child records into shared (96 float4, coalesced)
    __shared__ __align__(16) float4 sh4[NPB * 12];
    if (m < NPB * 12) {
        int k = m / 12, rr = m % 12;
        sh4[m] = reinterpret_cast<const float4*>(&g_child[t][n0 + k][0])[rr];
    }
    __syncthreads();

    float accf = 0.f;
#pragma unroll
    for (int k = 0; k < NPB; k++) {
        const unsigned long long* a2 =
            reinterpret_cast<const unsigned long long*>(&sh4[k * 12]);
        unsigned long long acc0 = 0ull, acc1 = 0ull;
#pragma unroll
        for (int p = 0; p < 22; p += 2) {
            ffma2(acc0, c2[p], a2[p]);
            ffma2(acc1, c2[p + 1], a2[p + 1]);
        }
        float2 s0 = unpack2(acc0);
        float2 s1 = unpack2(acc1);
        float cc = reinterpret_cast<const float*>(&sh4[k * 12])[44];
        float kl = (s0.x + s0.y) + (s1.x + s1.y) + (dm + cc);
        accf = fmaf(wv[k], kl, accf);
    }

    // fp32 warp reduce -> fp64 block partial, ticket finalize
#pragma unroll
    for (int off = 16; off; off >>= 1)
        accf += __shfl_down_sync(FULLM, accf, off);
    __shared__ float wsumf[4];
    __shared__ int islast;
    if ((m & 31) == 0) wsumf[m >> 5] = accf;
    __syncthreads();
    if (m == 0) {
        g_part[t][blockIdx.x] =
            (double)wsumf[0] + (double)wsumf[1] + (double)wsumf[2] + (double)wsumf[3];
        __threadfence();
        unsigned int tick = atomicAdd(&g_done, 1u);
        islast = (tick == 2u * NB - 1u) ? 1 : 0;
    }
    __syncthreads();
    if (islast) {
        __threadfence();
        double s0 = g_part[0][m] + g_part[0][m + 128];
        double s1 = g_part[1][m] + g_part[1][m + 128];
#pragma unroll
        for (int off = 16; off; off >>= 1) {
            s0 += __shfl_down_sync(FULLM, s0, off);
            s1 += __shfl_down_sync(FULLM, s1, off);
        }
        __shared__ double ws0[4], ws1[4];
        if ((m & 31) == 0) { ws0[m >> 5] = s0; ws1[m >> 5] = s1; }
        __syncthreads();
        if (m == 0) {
            double b  = ws0[0] + ws0[1] + ws0[2] + ws0[3];
            double mo = ws1[0] + ws1[1] + ws1[2] + ws1[3];
            out[0] = (float)(b + mo);
            out[1] = (float)b;
            out[2] = (float)mo;
        }
    }
}

// ----------------------------------------------------------------------------
extern "C" void kernel_launch(void* const* d_in, const int* in_sizes, int n_in,
                              void* d_out, int out_size) {
    const float* W              = (const float*)d_in[0];
    const float* mu_p           = (const float*)d_in[1];
    const float* sigma_p        = (const float*)d_in[2];
    const float* mu_q_parent    = (const float*)d_in[3];
    const float* sigma_q_parent = (const float*)d_in[4];
    const float* omega_child    = (const float*)d_in[5];
    const float* omega_parent   = (const float*)d_in[6];
    const float* mu_r           = (const float*)d_in[7];
    const float* sigma_r        = (const float*)d_in[8];
    const float* mu_s_parent    = (const float*)d_in[9];
    const float* sigma_s_parent = (const float*)d_in[10];
    const float* omega_m_child  = (const float*)d_in[11];
    const float* omega_m_parent = (const float*)d_in[12];

    precompute_kernel<<<136, 32>>>(mu_p, sigma_p, omega_child,
                                   mu_q_parent, sigma_q_parent, omega_parent,
                                   mu_r, sigma_r, omega_m_child,
                                   mu_s_parent, sigma_s_parent, omega_m_parent);
    pair_kernel<<<dim3(NB, 2), MM>>>(W, (float*)d_out);
}